// round 11
// baseline (speedup 1.0000x reference)
#include <cuda_runtime.h>
#include <cuda_bf16.h>
#include <cstdint>

// LRML: out[b] = -|| ue + rel - ie ||^2
// R10: R8's winning mapping (2 lanes/row, 16 rows/iteration, smem-staged
// weights, one-warp blocks) + 2 software-pipelined iterations per warp:
// ALL id loads and ALL 16 gather LDG.128s issue before any compute, so
// iter-1's DRAM latency hides behind iter-0's compute. 32 rows/warp,
// 512 blocks. Smem staging RESTORED (L1D is flushed per launch; direct
// __ldg weights cost an L2 trip inside the compute chain — R9 regression).

#define D 32
#define M 10
#define THREADS 32
#define ROWS_PER_ITER 16
#define NITER 2
#define ROWS_PER_BLOCK (ROWS_PER_ITER * NITER)   // 32

__device__ __forceinline__ void compute_rows(
    const float4 u0, const float4 u1, const float4 u2, const float4 u3,
    const float4 i0, const float4 i1, const float4 i2, const float4 i3,
    int p, const float4* __restrict__ sW, const float4* __restrict__ sMem,
    float* __restrict__ out, int row, bool valid)
{
    float ue[16] = {u0.x,u0.y,u0.z,u0.w, u1.x,u1.y,u1.z,u1.w,
                    u2.x,u2.y,u2.z,u2.w, u3.x,u3.y,u3.z,u3.w};
    float ie[16] = {i0.x,i0.y,i0.z,i0.w, i1.x,i1.y,i1.z,i1.w,
                    i2.x,i2.y,i2.z,i2.w, i3.x,i3.y,i3.z,i3.w};

    // max_norm=1 renorm (reduction = 1 shfl across the lane pair)
    float us = 0.f, is = 0.f;
    #pragma unroll
    for (int j = 0; j < 16; j++) { us = fmaf(ue[j], ue[j], us); is = fmaf(ie[j], ie[j], is); }
    us += __shfl_xor_sync(0xFFFFFFFFu, us, 1);
    is += __shfl_xor_sync(0xFFFFFFFFu, is, 1);
    const float un = sqrtf(us), in = sqrtf(is);
    const float uscale = (un > 1.0f) ? (1.0f / un) : 1.0f;
    const float iscale = (in > 1.0f) ? (1.0f / in) : 1.0f;
    #pragma unroll
    for (int j = 0; j < 16; j++) { ue[j] *= uscale; ie[j] *= iscale; }

    float joint[16];
    #pragma unroll
    for (int j = 0; j < 16; j++) joint[j] = ue[j] * ie[j];

    // scores[m] = joint . W_att[m] (16-dim partial + 1 shfl)
    float sc[M];
    #pragma unroll
    for (int m = 0; m < M; m++) {
        const float4* w = &sW[m * 8 + p * 4];
        const float4 w0 = w[0], w1 = w[1], w2 = w[2], w3 = w[3];
        float a = joint[0] * w0.x;
        float b = joint[1] * w0.y;
        a = fmaf(joint[2],  w0.z, a);
        b = fmaf(joint[3],  w0.w, b);
        a = fmaf(joint[4],  w1.x, a);
        b = fmaf(joint[5],  w1.y, b);
        a = fmaf(joint[6],  w1.z, a);
        b = fmaf(joint[7],  w1.w, b);
        a = fmaf(joint[8],  w2.x, a);
        b = fmaf(joint[9],  w2.y, b);
        a = fmaf(joint[10], w2.z, a);
        b = fmaf(joint[11], w2.w, b);
        a = fmaf(joint[12], w3.x, a);
        b = fmaf(joint[13], w3.y, b);
        a = fmaf(joint[14], w3.z, a);
        b = fmaf(joint[15], w3.w, b);
        float s = a + b;
        s += __shfl_xor_sync(0xFFFFFFFFu, s, 1);
        sc[m] = s;
    }

    // softmax over M=10, redundantly in both lanes of the pair
    float mx = sc[0];
    #pragma unroll
    for (int m = 1; m < M; m++) mx = fmaxf(mx, sc[m]);
    float denom = 0.0f;
    #pragma unroll
    for (int m = 0; m < M; m++) { sc[m] = __expf(sc[m] - mx); denom += sc[m]; }
    const float inv_denom = 1.0f / denom;

    // rel[j] = sum_m sc[m] * memory[m][p*16+j]; normalization folded into dist
    float rel[16];
    #pragma unroll
    for (int j = 0; j < 16; j++) rel[j] = 0.0f;
    #pragma unroll
    for (int m = 0; m < M; m++) {
        const float4* mmp = &sMem[m * 8 + p * 4];
        const float4 m0 = mmp[0], m1 = mmp[1], m2 = mmp[2], m3 = mmp[3];
        const float s = sc[m];
        rel[0]  = fmaf(s, m0.x, rel[0]);
        rel[1]  = fmaf(s, m0.y, rel[1]);
        rel[2]  = fmaf(s, m0.z, rel[2]);
        rel[3]  = fmaf(s, m0.w, rel[3]);
        rel[4]  = fmaf(s, m1.x, rel[4]);
        rel[5]  = fmaf(s, m1.y, rel[5]);
        rel[6]  = fmaf(s, m1.z, rel[6]);
        rel[7]  = fmaf(s, m1.w, rel[7]);
        rel[8]  = fmaf(s, m2.x, rel[8]);
        rel[9]  = fmaf(s, m2.y, rel[9]);
        rel[10] = fmaf(s, m2.z, rel[10]);
        rel[11] = fmaf(s, m2.w, rel[11]);
        rel[12] = fmaf(s, m3.x, rel[12]);
        rel[13] = fmaf(s, m3.y, rel[13]);
        rel[14] = fmaf(s, m3.z, rel[14]);
        rel[15] = fmaf(s, m3.w, rel[15]);
    }

    float dist = 0.0f;
    #pragma unroll
    for (int j = 0; j < 16; j++) {
        const float diff = fmaf(rel[j], inv_denom, ue[j] - ie[j]);
        dist = fmaf(diff, diff, dist);
    }
    dist += __shfl_xor_sync(0xFFFFFFFFu, dist, 1);

    if (p == 0 && valid) out[row] = -dist;
}

__global__ __launch_bounds__(THREADS)
void lrml_kernel(const int* __restrict__ user_ids,
                 const int* __restrict__ item_ids,
                 const float* __restrict__ user_emb,
                 const float* __restrict__ item_emb,
                 const float* __restrict__ W_att,
                 const float* __restrict__ memory,
                 float* __restrict__ out,
                 int B)
{
    __shared__ float4 sW[M * 8];    // 10 rows x 32 floats as float4
    __shared__ float4 sMem[M * 8];

    const int lane = threadIdx.x & 31;
    const int p    = lane & 1;        // which 16-dim half
    const int r    = lane >> 1;       // row within iteration (0..15)

    int row0 = blockIdx.x * ROWS_PER_BLOCK + r;
    int row1 = row0 + ROWS_PER_ITER;
    const bool v0 = (row0 < B);
    const bool v1 = (row1 < B);
    if (row0 >= B) row0 = B - 1;
    if (row1 >= B) row1 = B - 1;

    // ---- Phase 1: issue ALL loads up front ----
    const int uid0 = __ldg(&user_ids[row0]);
    const int iid0 = __ldg(&item_ids[row0]);
    const int uid1 = __ldg(&user_ids[row1]);
    const int iid1 = __ldg(&item_ids[row1]);

    // Weight staging overlaps the id round trip (independent addresses).
    #pragma unroll
    for (int idx = lane; idx < M * 8; idx += THREADS) {
        sW[idx]   = __ldg(((const float4*)W_att) + idx);
        sMem[idx] = __ldg(((const float4*)memory) + idx);
    }

    // Gathers for BOTH iterations (16 LDG.128 in flight per lane-pair half).
    const float4* up0 = (const float4*)(user_emb + (size_t)uid0 * D + p * 16);
    const float4* ip0 = (const float4*)(item_emb + (size_t)iid0 * D + p * 16);
    const float4* up1 = (const float4*)(user_emb + (size_t)uid1 * D + p * 16);
    const float4* ip1 = (const float4*)(item_emb + (size_t)iid1 * D + p * 16);

    const float4 a0 = __ldg(up0),     a1 = __ldg(up0 + 1),
                 a2 = __ldg(up0 + 2), a3 = __ldg(up0 + 3);
    const float4 b0 = __ldg(ip0),     b1 = __ldg(ip0 + 1),
                 b2 = __ldg(ip0 + 2), b3 = __ldg(ip0 + 3);
    const float4 c0 = __ldg(up1),     c1 = __ldg(up1 + 1),
                 c2 = __ldg(up1 + 2), c3 = __ldg(up1 + 3);
    const float4 d0 = __ldg(ip1),     d1 = __ldg(ip1 + 1),
                 d2 = __ldg(ip1 + 2), d3 = __ldg(ip1 + 3);

    __syncwarp();

    // ---- Phase 2: compute; iter-1's loads stay in flight during iter-0 ----
    compute_rows(a0, a1, a2, a3, b0, b1, b2, b3, p, sW, sMem, out, row0, v0);
    compute_rows(c0, c1, c2, c3, d0, d1, d2, d3, p, sW, sMem, out, row1, v1);
}

extern "C" void kernel_launch(void* const* d_in, const int* in_sizes, int n_in,
                              void* d_out, int out_size)
{
    const int*   user_ids = (const int*)  d_in[0];
    const int*   item_ids = (const int*)  d_in[1];
    const float* user_emb = (const float*)d_in[2];
    const float* item_emb = (const float*)d_in[3];
    const float* W_att    = (const float*)d_in[4];
    const float* memory   = (const float*)d_in[5];
    float*       out      = (float*)d_out;

    const int B = in_sizes[0];
    const int grid = (B + ROWS_PER_BLOCK - 1) / ROWS_PER_BLOCK;  // 512
    lrml_kernel<<<grid, THREADS>>>(user_ids, item_ids, user_emb, item_emb,
                                   W_att, memory, out, B);
}

// round 14
// speedup vs baseline: 1.2070x; 1.2070x over previous
#include <cuda_runtime.h>
#include <cuda_bf16.h>
#include <cstdint>

// LRML: out[b] = -|| ue + rel - ie ||^2
// R12: 1 lane per row -> ZERO shuffles. Each lane loads its entire row
// (128B per table, 8x LDG.128, same line count as the 2-lane mapping)
// and computes norms/scores/softmax/rel/dist fully scalar with 4-way
// accumulator splits for ILP. 32 rows/warp, 512 one-warp blocks.
// Weights staged in smem (L1D flushed per launch; R9 showed direct __ldg
// weights cost an L2 trip inside the chain). Output store is coalesced.

#define D 32
#define M 10
#define THREADS 32
#define ROWS_PER_BLOCK 32

__global__ __launch_bounds__(THREADS)
void lrml_kernel(const int* __restrict__ user_ids,
                 const int* __restrict__ item_ids,
                 const float* __restrict__ user_emb,
                 const float* __restrict__ item_emb,
                 const float* __restrict__ W_att,
                 const float* __restrict__ memory,
                 float* __restrict__ out,
                 int B)
{
    __shared__ float4 sW[M * 8];    // 10 rows x 32 floats
    __shared__ float4 sMem[M * 8];

    const int lane = threadIdx.x;
    int row = blockIdx.x * ROWS_PER_BLOCK + lane;
    const bool valid = (row < B);
    if (!valid) row = B - 1;

    // ids first: their latency overlaps weight staging
    const int uid = __ldg(&user_ids[row]);
    const int iid = __ldg(&item_ids[row]);

    // Stage weights (2.5KB total, L2-hot): 160 float4 / 32 lanes = 5 each
    #pragma unroll
    for (int idx = lane; idx < M * 8; idx += THREADS) {
        sW[idx]   = __ldg(((const float4*)W_att) + idx);
        sMem[idx] = __ldg(((const float4*)memory) + idx);
    }

    // Full-row gathers: 8 independent LDG.128 per lane (one 128B line per table)
    const float4* up = (const float4*)(user_emb + (size_t)uid * D);
    const float4* ip = (const float4*)(item_emb + (size_t)iid * D);
    float4 uv[8], iv[8];
    #pragma unroll
    for (int k = 0; k < 8; k++) uv[k] = __ldg(up + k);
    #pragma unroll
    for (int k = 0; k < 8; k++) iv[k] = __ldg(ip + k);

    __syncwarp();

    float ue[D], ie[D];
    #pragma unroll
    for (int k = 0; k < 8; k++) {
        ue[4*k+0] = uv[k].x; ue[4*k+1] = uv[k].y; ue[4*k+2] = uv[k].z; ue[4*k+3] = uv[k].w;
        ie[4*k+0] = iv[k].x; ie[4*k+1] = iv[k].y; ie[4*k+2] = iv[k].z; ie[4*k+3] = iv[k].w;
    }

    // ---- max_norm=1 renorm (4-way accumulator split, no reductions) ----
    float us0 = 0.f, us1 = 0.f, us2 = 0.f, us3 = 0.f;
    float is0 = 0.f, is1 = 0.f, is2 = 0.f, is3 = 0.f;
    #pragma unroll
    for (int j = 0; j < D; j += 4) {
        us0 = fmaf(ue[j+0], ue[j+0], us0);
        us1 = fmaf(ue[j+1], ue[j+1], us1);
        us2 = fmaf(ue[j+2], ue[j+2], us2);
        us3 = fmaf(ue[j+3], ue[j+3], us3);
        is0 = fmaf(ie[j+0], ie[j+0], is0);
        is1 = fmaf(ie[j+1], ie[j+1], is1);
        is2 = fmaf(ie[j+2], ie[j+2], is2);
        is3 = fmaf(ie[j+3], ie[j+3], is3);
    }
    const float un = sqrtf((us0 + us1) + (us2 + us3));
    const float in = sqrtf((is0 + is1) + (is2 + is3));
    const float uscale = (un > 1.0f) ? (1.0f / un) : 1.0f;
    const float iscale = (in > 1.0f) ? (1.0f / in) : 1.0f;
    #pragma unroll
    for (int j = 0; j < D; j++) { ue[j] *= uscale; ie[j] *= iscale; }

    float joint[D];
    #pragma unroll
    for (int j = 0; j < D; j++) joint[j] = ue[j] * ie[j];

    // ---- scores[m] = joint . W_att[m]  (smem broadcast reads, no shfl) ----
    float sc[M];
    #pragma unroll
    for (int m = 0; m < M; m++) {
        const float4* w = &sW[m * 8];
        float a0 = 0.f, a1 = 0.f, a2 = 0.f, a3 = 0.f;
        #pragma unroll
        for (int k = 0; k < 8; k++) {
            const float4 wk = w[k];
            a0 = fmaf(joint[4*k+0], wk.x, a0);
            a1 = fmaf(joint[4*k+1], wk.y, a1);
            a2 = fmaf(joint[4*k+2], wk.z, a2);
            a3 = fmaf(joint[4*k+3], wk.w, a3);
        }
        sc[m] = (a0 + a1) + (a2 + a3);
    }

    // ---- softmax over M=10 (scalar) ----
    float mx = sc[0];
    #pragma unroll
    for (int m = 1; m < M; m++) mx = fmaxf(mx, sc[m]);
    float denom = 0.0f;
    #pragma unroll
    for (int m = 0; m < M; m++) { sc[m] = __expf(sc[m] - mx); denom += sc[m]; }
    const float inv_denom = 1.0f / denom;

    // ---- rel[j] = sum_m sc[m]*memory[m][j]; normalization folded into dist
    float rel[D];
    #pragma unroll
    for (int j = 0; j < D; j++) rel[j] = 0.0f;
    #pragma unroll
    for (int m = 0; m < M; m++) {
        const float4* mm = &sMem[m * 8];
        const float s = sc[m];
        #pragma unroll
        for (int k = 0; k < 8; k++) {
            const float4 mk = mm[k];
            rel[4*k+0] = fmaf(s, mk.x, rel[4*k+0]);
            rel[4*k+1] = fmaf(s, mk.y, rel[4*k+1]);
            rel[4*k+2] = fmaf(s, mk.z, rel[4*k+2]);
            rel[4*k+3] = fmaf(s, mk.w, rel[4*k+3]);
        }
    }

    // ---- dist (4-way split) ----
    float d0 = 0.f, d1 = 0.f, d2 = 0.f, d3 = 0.f;
    #pragma unroll
    for (int j = 0; j < D; j += 4) {
        const float e0 = fmaf(rel[j+0], inv_denom, ue[j+0] - ie[j+0]);
        const float e1 = fmaf(rel[j+1], inv_denom, ue[j+1] - ie[j+1]);
        const float e2 = fmaf(rel[j+2], inv_denom, ue[j+2] - ie[j+2]);
        const float e3 = fmaf(rel[j+3], inv_denom, ue[j+3] - ie[j+3]);
        d0 = fmaf(e0, e0, d0);
        d1 = fmaf(e1, e1, d1);
        d2 = fmaf(e2, e2, d2);
        d3 = fmaf(e3, e3, d3);
    }
    const float dist = (d0 + d1) + (d2 + d3);

    if (valid) out[row] = -dist;   // coalesced: lane == row offset
}

extern "C" void kernel_launch(void* const* d_in, const int* in_sizes, int n_in,
                              void* d_out, int out_size)
{
    const int*   user_ids = (const int*)  d_in[0];
    const int*   item_ids = (const int*)  d_in[1];
    const float* user_emb = (const float*)d_in[2];
    const float* item_emb = (const float*)d_in[3];
    const float* W_att    = (const float*)d_in[4];
    const float* memory   = (const float*)d_in[5];
    float*       out      = (float*)d_out;

    const int B = in_sizes[0];
    const int grid = (B + ROWS_PER_BLOCK - 1) / ROWS_PER_BLOCK;  // 512
    lrml_kernel<<<grid, THREADS>>>(user_ids, item_ids, user_emb, item_emb,
                                   W_att, memory, out, B);
}

// round 15
// speedup vs baseline: 1.4454x; 1.1975x over previous
#include <cuda_runtime.h>
#include <cuda_bf16.h>
#include <cstdint>

// LRML: out[b] = -|| ue + rel - ie ||^2
// R15: R8's winning structure (2 lanes/row, 16 rows/warp, 1024 one-warp
// blocks, smem-staged weights) with ALL heavy fp32 math converted to
// packed fma.rn.f32x2 / mul.rn.f32x2 (Blackwell f32x2 pipe, PTX-only).
// float4/ulonglong2 loads already deliver operands as adjacent register
// pairs = f32x2 layout, so packing costs no MOVs; only scalar broadcasts
// (renorm scales, softmax weights, -1, 1/denom) are packed explicitly.
// Per-lane FMA-class instructions drop ~450 -> ~230, bit-identical math.

#define D 32
#define M 10
#define THREADS 32
#define ROWS_PER_WARP 16

typedef unsigned long long u64;

__device__ __forceinline__ u64 fma2(u64 a, u64 b, u64 c) {
    u64 d; asm("fma.rn.f32x2 %0, %1, %2, %3;" : "=l"(d) : "l"(a), "l"(b), "l"(c)); return d;
}
__device__ __forceinline__ u64 mul2(u64 a, u64 b) {
    u64 d; asm("mul.rn.f32x2 %0, %1, %2;" : "=l"(d) : "l"(a), "l"(b)); return d;
}
__device__ __forceinline__ u64 pack2(float lo, float hi) {
    u64 r; asm("mov.b64 %0, {%1, %2};" : "=l"(r) : "f"(lo), "f"(hi)); return r;
}
__device__ __forceinline__ float2 unpack2(u64 v) {
    float lo, hi; asm("mov.b64 {%0, %1}, %2;" : "=f"(lo), "=f"(hi) : "l"(v));
    return make_float2(lo, hi);
}

__global__ __launch_bounds__(THREADS)
void lrml_kernel(const int* __restrict__ user_ids,
                 const int* __restrict__ item_ids,
                 const float* __restrict__ user_emb,
                 const float* __restrict__ item_emb,
                 const float* __restrict__ W_att,
                 const float* __restrict__ memory,
                 float* __restrict__ out,
                 int B)
{
    // 10 rows x 32 floats, as 16B chunks = {f32x2, f32x2}
    __shared__ ulonglong2 sW[M * 8];
    __shared__ ulonglong2 sMem[M * 8];

    const int lane = threadIdx.x & 31;
    const int p    = lane & 1;        // which 16-dim half
    const int r    = lane >> 1;       // row within warp (0..15)

    int row = blockIdx.x * ROWS_PER_WARP + r;
    const bool valid = (row < B);
    if (!valid) row = B - 1;

    // ids first: latency overlaps weight staging
    const int uid = __ldg(&user_ids[row]);
    const int iid = __ldg(&item_ids[row]);

    // Stage weights (2.5KB, L2-hot): 160 chunks / 32 lanes = 5 each
    #pragma unroll
    for (int idx = lane; idx < M * 8; idx += THREADS) {
        sW[idx]   = __ldg(((const ulonglong2*)W_att) + idx);
        sMem[idx] = __ldg(((const ulonglong2*)memory) + idx);
    }

    // Gathers: 64B half-row per lane per table (4x LDG.128 each);
    // both halves of a row share one 128B line.
    const ulonglong2* up = (const ulonglong2*)(user_emb + (size_t)uid * D + p * 16);
    const ulonglong2* ip = (const ulonglong2*)(item_emb + (size_t)iid * D + p * 16);
    const ulonglong2 ua0 = __ldg(up),     ua1 = __ldg(up + 1),
                     ua2 = __ldg(up + 2), ua3 = __ldg(up + 3);
    const ulonglong2 ia0 = __ldg(ip),     ia1 = __ldg(ip + 1),
                     ia2 = __ldg(ip + 2), ia3 = __ldg(ip + 3);

    __syncwarp();

    u64 ue2[8] = {ua0.x, ua0.y, ua1.x, ua1.y, ua2.x, ua2.y, ua3.x, ua3.y};
    u64 ie2[8] = {ia0.x, ia0.y, ia1.x, ia1.y, ia2.x, ia2.y, ia3.x, ia3.y};

    // ---- max_norm=1 renorm: packed squares, 2 accumulators, 1 shfl ----
    u64 uaccA = mul2(ue2[0], ue2[0]);
    u64 uaccB = mul2(ue2[1], ue2[1]);
    u64 iaccA = mul2(ie2[0], ie2[0]);
    u64 iaccB = mul2(ie2[1], ie2[1]);
    #pragma unroll
    for (int k = 2; k < 8; k += 2) {
        uaccA = fma2(ue2[k],   ue2[k],   uaccA);
        uaccB = fma2(ue2[k+1], ue2[k+1], uaccB);
        iaccA = fma2(ie2[k],   ie2[k],   iaccA);
        iaccB = fma2(ie2[k+1], ie2[k+1], iaccB);
    }
    const float2 ut0 = unpack2(uaccA), ut1 = unpack2(uaccB);
    const float2 it0 = unpack2(iaccA), it1 = unpack2(iaccB);
    float us = (ut0.x + ut0.y) + (ut1.x + ut1.y);
    float is = (it0.x + it0.y) + (it1.x + it1.y);
    us += __shfl_xor_sync(0xFFFFFFFFu, us, 1);
    is += __shfl_xor_sync(0xFFFFFFFFu, is, 1);
    const float un = sqrtf(us), in = sqrtf(is);
    const float uscale = (un > 1.0f) ? (1.0f / un) : 1.0f;
    const float iscale = (in > 1.0f) ? (1.0f / in) : 1.0f;
    const u64 us2 = pack2(uscale, uscale);
    const u64 is2 = pack2(iscale, iscale);
    #pragma unroll
    for (int k = 0; k < 8; k++) { ue2[k] = mul2(ue2[k], us2); ie2[k] = mul2(ie2[k], is2); }

    u64 joint2[8];
    #pragma unroll
    for (int k = 0; k < 8; k++) joint2[k] = mul2(ue2[k], ie2[k]);

    // ---- scores[m] = joint . W_att[m]: 8 packed FMAs + 1 shfl per m ----
    float sc[M];
    #pragma unroll
    for (int m = 0; m < M; m++) {
        const ulonglong2* w = &sW[m * 8 + p * 4];
        const ulonglong2 w0 = w[0], w1 = w[1], w2 = w[2], w3 = w[3];
        u64 a = mul2(joint2[0], w0.x);
        u64 b = mul2(joint2[1], w0.y);
        a = fma2(joint2[2], w1.x, a);
        b = fma2(joint2[3], w1.y, b);
        a = fma2(joint2[4], w2.x, a);
        b = fma2(joint2[5], w2.y, b);
        a = fma2(joint2[6], w3.x, a);
        b = fma2(joint2[7], w3.y, b);
        const float2 ta = unpack2(a), tb = unpack2(b);
        float s = (ta.x + ta.y) + (tb.x + tb.y);
        s += __shfl_xor_sync(0xFFFFFFFFu, s, 1);
        sc[m] = s;
    }

    // ---- softmax over M=10 (scalar, redundant in both lanes of pair) ----
    float mx = sc[0];
    #pragma unroll
    for (int m = 1; m < M; m++) mx = fmaxf(mx, sc[m]);
    float denom = 0.0f;
    #pragma unroll
    for (int m = 0; m < M; m++) { sc[m] = __expf(sc[m] - mx); denom += sc[m]; }
    const float inv_denom = 1.0f / denom;

    // ---- rel = sum_m sc[m] * memory[m]: packed accumulate ----
    u64 rel2[8] = {0, 0, 0, 0, 0, 0, 0, 0};   // 0 bits == {0.0f, 0.0f}
    #pragma unroll
    for (int m = 0; m < M; m++) {
        const ulonglong2* mm = &sMem[m * 8 + p * 4];
        const ulonglong2 m0 = mm[0], m1 = mm[1], m2 = mm[2], m3 = mm[3];
        const u64 s2 = pack2(sc[m], sc[m]);
        rel2[0] = fma2(s2, m0.x, rel2[0]);
        rel2[1] = fma2(s2, m0.y, rel2[1]);
        rel2[2] = fma2(s2, m1.x, rel2[2]);
        rel2[3] = fma2(s2, m1.y, rel2[3]);
        rel2[4] = fma2(s2, m2.x, rel2[4]);
        rel2[5] = fma2(s2, m2.y, rel2[5]);
        rel2[6] = fma2(s2, m3.x, rel2[6]);
        rel2[7] = fma2(s2, m3.y, rel2[7]);
    }

    // ---- dist: diff = (ue - ie) + rel * inv_denom, packed ----
    const u64 neg1  = pack2(-1.0f, -1.0f);
    const u64 invd2 = pack2(inv_denom, inv_denom);
    u64 dA = 0, dB = 0;
    #pragma unroll
    for (int k = 0; k < 8; k += 2) {
        const u64 baseA = fma2(ie2[k],   neg1, ue2[k]);     // ue - ie
        const u64 baseB = fma2(ie2[k+1], neg1, ue2[k+1]);
        const u64 diffA = fma2(rel2[k],   invd2, baseA);
        const u64 diffB = fma2(rel2[k+1], invd2, baseB);
        dA = fma2(diffA, diffA, dA);
        dB = fma2(diffB, diffB, dB);
    }
    const float2 tA = unpack2(dA), tB = unpack2(dB);
    float dist = (tA.x + tA.y) + (tB.x + tB.y);
    dist += __shfl_xor_sync(0xFFFFFFFFu, dist, 1);

    if (p == 0 && valid) out[row] = -dist;
}

extern "C" void kernel_launch(void* const* d_in, const int* in_sizes, int n_in,
                              void* d_out, int out_size)
{
    const int*   user_ids = (const int*)  d_in[0];
    const int*   item_ids = (const int*)  d_in[1];
    const float* user_emb = (const float*)d_in[2];
    const float* item_emb = (const float*)d_in[3];
    const float* W_att    = (const float*)d_in[4];
    const float* memory   = (const float*)d_in[5];
    float*       out      = (float*)d_out;

    const int B = in_sizes[0];
    const int grid = (B + ROWS_PER_WARP - 1) / ROWS_PER_WARP;  // 1024
    lrml_kernel<<<grid, THREADS>>>(user_ids, item_ids, user_emb, item_emb,
                                   W_att, memory, out, B);
}

// round 16
// speedup vs baseline: 1.6538x; 1.1442x over previous
#include <cuda_runtime.h>
#include <cuda_bf16.h>
#include <cstdint>

// LRML: out[b] = -|| ue + rel - ie ||^2
// R16 = R8 champion (2 lanes/row, 16 rows/warp, 1024 one-warp blocks,
// smem-staged weights, scalar FMA) + serial-chain trims:
//  - renorm scale via single MUFU.RSQ: scale = (us>1) ? rsqrtf(us) : 1
//  - softmax WITHOUT max-subtraction (post-renorm |score| <~ 1, exp safe);
//    each exp overlaps the remaining score reductions instead of joining
//    on a 10-score max first.

#define D 32
#define M 10
#define THREADS 32
#define ROWS_PER_WARP 16

__global__ __launch_bounds__(THREADS)
void lrml_kernel(const int* __restrict__ user_ids,
                 const int* __restrict__ item_ids,
                 const float* __restrict__ user_emb,
                 const float* __restrict__ item_emb,
                 const float* __restrict__ W_att,
                 const float* __restrict__ memory,
                 float* __restrict__ out,
                 int B)
{
    __shared__ float4 sW[M * 8];    // 10 rows x 32 floats as float4
    __shared__ float4 sMem[M * 8];

    const int lane = threadIdx.x & 31;
    const int p    = lane & 1;        // which 16-dim half
    const int r    = lane >> 1;       // row within warp (0..15)

    int row = blockIdx.x * ROWS_PER_WARP + r;
    const bool valid = (row < B);
    if (!valid) row = B - 1;

    // ids first: their latency overlaps the weight staging below
    const int uid = __ldg(&user_ids[row]);
    const int iid = __ldg(&item_ids[row]);

    // Stage weights (2.5KB, L2-hot): 160 float4 / 32 lanes = 5 each
    #pragma unroll
    for (int idx = lane; idx < M * 8; idx += THREADS) {
        sW[idx]   = __ldg(((const float4*)W_att) + idx);
        sMem[idx] = __ldg(((const float4*)memory) + idx);
    }

    // Gathers: each lane reads its 64B half-row from each table (4x LDG.128);
    // both halves of a row share one 128B line.
    const float4* up = (const float4*)(user_emb + (size_t)uid * D + p * 16);
    const float4* ip = (const float4*)(item_emb + (size_t)iid * D + p * 16);
    const float4 u0 = __ldg(up);
    const float4 u1 = __ldg(up + 1);
    const float4 u2 = __ldg(up + 2);
    const float4 u3 = __ldg(up + 3);
    const float4 i0 = __ldg(ip);
    const float4 i1 = __ldg(ip + 1);
    const float4 i2 = __ldg(ip + 2);
    const float4 i3 = __ldg(ip + 3);

    __syncwarp();

    float ue[16] = {u0.x,u0.y,u0.z,u0.w, u1.x,u1.y,u1.z,u1.w,
                    u2.x,u2.y,u2.z,u2.w, u3.x,u3.y,u3.z,u3.w};
    float ie[16] = {i0.x,i0.y,i0.z,i0.w, i1.x,i1.y,i1.z,i1.w,
                    i2.x,i2.y,i2.z,i2.w, i3.x,i3.y,i3.z,i3.w};

    // max_norm=1 renorm; single MUFU.RSQ per embedding (us>1 <=> norm>1)
    float us = 0.f, is = 0.f;
    #pragma unroll
    for (int j = 0; j < 16; j++) { us = fmaf(ue[j], ue[j], us); is = fmaf(ie[j], ie[j], is); }
    us += __shfl_xor_sync(0xFFFFFFFFu, us, 1);
    is += __shfl_xor_sync(0xFFFFFFFFu, is, 1);
    const float uscale = (us > 1.0f) ? rsqrtf(us) : 1.0f;
    const float iscale = (is > 1.0f) ? rsqrtf(is) : 1.0f;
    #pragma unroll
    for (int j = 0; j < 16; j++) { ue[j] *= uscale; ie[j] *= iscale; }

    float joint[16];
    #pragma unroll
    for (int j = 0; j < 16; j++) joint[j] = ue[j] * ie[j];

    // scores[m] = joint . W_att[m]; exp applied immediately (no max shift:
    // post-renorm ||ue*ie||<=1 and ||W_m||~1 so |score| <~ 1, exp safe).
    float sc[M];
    float denom = 0.0f;
    #pragma unroll
    for (int m = 0; m < M; m++) {
        const float4* w = &sW[m * 8 + p * 4];
        const float4 w0 = w[0], w1 = w[1], w2 = w[2], w3 = w[3];
        float a = joint[0] * w0.x;
        float b = joint[1] * w0.y;
        a = fmaf(joint[2],  w0.z, a);
        b = fmaf(joint[3],  w0.w, b);
        a = fmaf(joint[4],  w1.x, a);
        b = fmaf(joint[5],  w1.y, b);
        a = fmaf(joint[6],  w1.z, a);
        b = fmaf(joint[7],  w1.w, b);
        a = fmaf(joint[8],  w2.x, a);
        b = fmaf(joint[9],  w2.y, b);
        a = fmaf(joint[10], w2.z, a);
        b = fmaf(joint[11], w2.w, b);
        a = fmaf(joint[12], w3.x, a);
        b = fmaf(joint[13], w3.y, b);
        a = fmaf(joint[14], w3.z, a);
        b = fmaf(joint[15], w3.w, b);
        float s = a + b;
        s += __shfl_xor_sync(0xFFFFFFFFu, s, 1);
        const float e = __expf(s);
        sc[m] = e;
        denom += e;
    }
    const float inv_denom = 1.0f / denom;

    // rel[j] = sum_m sc[m] * memory[m][p*16+j]; normalization folded into dist
    float rel[16];
    #pragma unroll
    for (int j = 0; j < 16; j++) rel[j] = 0.0f;
    #pragma unroll
    for (int m = 0; m < M; m++) {
        const float4* mmp = &sMem[m * 8 + p * 4];
        const float4 m0 = mmp[0], m1 = mmp[1], m2 = mmp[2], m3 = mmp[3];
        const float s = sc[m];
        rel[0]  = fmaf(s, m0.x, rel[0]);
        rel[1]  = fmaf(s, m0.y, rel[1]);
        rel[2]  = fmaf(s, m0.z, rel[2]);
        rel[3]  = fmaf(s, m0.w, rel[3]);
        rel[4]  = fmaf(s, m1.x, rel[4]);
        rel[5]  = fmaf(s, m1.y, rel[5]);
        rel[6]  = fmaf(s, m1.z, rel[6]);
        rel[7]  = fmaf(s, m1.w, rel[7]);
        rel[8]  = fmaf(s, m2.x, rel[8]);
        rel[9]  = fmaf(s, m2.y, rel[9]);
        rel[10] = fmaf(s, m2.z, rel[10]);
        rel[11] = fmaf(s, m2.w, rel[11]);
        rel[12] = fmaf(s, m3.x, rel[12]);
        rel[13] = fmaf(s, m3.y, rel[13]);
        rel[14] = fmaf(s, m3.z, rel[14]);
        rel[15] = fmaf(s, m3.w, rel[15]);
    }

    float dist = 0.0f;
    #pragma unroll
    for (int j = 0; j < 16; j++) {
        const float diff = fmaf(rel[j], inv_denom, ue[j] - ie[j]);
        dist = fmaf(diff, diff, dist);
    }
    dist += __shfl_xor_sync(0xFFFFFFFFu, dist, 1);

    if (p == 0 && valid) out[row] = -dist;
}

extern "C" void kernel_launch(void* const* d_in, const int* in_sizes, int n_in,
                              void* d_out, int out_size)
{
    const int*   user_ids = (const int*)  d_in[0];
    const int*   item_ids = (const int*)  d_in[1];
    const float* user_emb = (const float*)d_in[2];
    const float* item_emb = (const float*)d_in[3];
    const float* W_att    = (const float*)d_in[4];
    const float* memory   = (const float*)d_in[5];
    float*       out      = (float*)d_out;

    const int B = in_sizes[0];
    const int grid = (B + ROWS_PER_WARP - 1) / ROWS_PER_WARP;  // 1024
    lrml_kernel<<<grid, THREADS>>>(user_ids, item_ids, user_emb, item_emb,
                                   W_att, memory, out, B);
}